// round 2
// baseline (speedup 1.0000x reference)
#include <cuda_runtime.h>
#include <cstdint>

#define NPTS  8192
#define TPB   256
#define JCH   1024
#define GRIDX (NPTS / TPB)      // 32
#define GRIDY (NPTS / JCH)      // 8
#define NBLK  (GRIDX * GRIDY)   // 256
#define MIN_DISTF 0.1f

// per-block partials (written by every block every launch -> no pre-zero needed)
__device__ float g_pen[NBLK];
__device__ float g_mse[NBLK];
__device__ int   g_cnt = 0;     // arrival counter; last block resets it to 0

__device__ __forceinline__ uint32_t smem_u32(const void* p) {
    uint32_t a;
    asm("{ .reg .u64 t; cvta.to.shared.u64 t, %1; cvt.u32.u64 %0, t; }" : "=r"(a) : "l"(p));
    return a;
}

__device__ __forceinline__ uint64_t pack2(float x) {
    uint64_t v;
    asm("mov.b64 %0, {%1, %1};" : "=l"(v) : "r"(__float_as_uint(x)));
    return v;
}

__global__ void __launch_bounds__(TPB, 1) k_fused(const float4* __restrict__ pred4,
                                                  const float4* __restrict__ targ4,
                                                  const float2* __restrict__ pts,
                                                  float* __restrict__ out) {
    __shared__ __align__(16) float nx[JCH];
    __shared__ __align__(16) float ny[JCH];
    __shared__ float redp[TPB / 32];
    __shared__ float redm[TPB / 32];
    __shared__ int   lastFlag;

    const int tid   = threadIdx.x;
    const int bid   = blockIdx.y * gridDim.x + blockIdx.x;
    const int ibase = blockIdx.x * TPB;
    const int jbase = blockIdx.y * JCH;

    // ---- MSE slice: 16 float4 per block (4096 total) ----
    float mse = 0.f;
    if (tid < 16) {
        float4 a = pred4[bid * 16 + tid];
        float4 b = targ4[bid * 16 + tid];
        float d0 = a.x - b.x, d1 = a.y - b.y, d2 = a.z - b.z, d3 = a.w - b.w;
        mse = fmaf(d0, d0, fmaf(d1, d1, fmaf(d2, d2, d3 * d3)));
    }

    // ---- pairwise penalty: strict upper triangle ----
    float acc0 = 0.f, acc1 = 0.f;
    const bool active = (jbase + JCH > ibase);  // block-uniform
    if (active) {
        const int    i  = ibase + tid;
        const float2 pi = pts[i];
        const uint64_t pix2 = pack2(pi.x);
        const uint64_t piy2 = pack2(pi.y);

        for (int k = tid; k < JCH; k += TPB) {
            float2 p = pts[jbase + k];
            nx[k] = -p.x;
            ny[k] = -p.y;
        }
        __syncthreads();

        const uint32_t nxb = smem_u32(nx);
        const uint32_t nyb = smem_u32(ny);

        if (jbase >= ibase + TPB) {
            // entirely above the diagonal: no per-pair index check
#pragma unroll 8
            for (int k = 0; k < JCH; k += 2) {
                uint64_t xk, yk, dxp, dyp, t, d2p;
                asm("ld.shared.b64 %0, [%1];" : "=l"(xk) : "r"(nxb + k * 4));
                asm("ld.shared.b64 %0, [%1];" : "=l"(yk) : "r"(nyb + k * 4));
                asm("add.rn.f32x2 %0, %1, %2;" : "=l"(dxp) : "l"(pix2), "l"(xk));
                asm("add.rn.f32x2 %0, %1, %2;" : "=l"(dyp) : "l"(piy2), "l"(yk));
                asm("mul.rn.f32x2 %0, %1, %1;" : "=l"(t)   : "l"(dxp));
                asm("fma.rn.f32x2 %0, %1, %1, %2;" : "=l"(d2p) : "l"(dyp), "l"(t));
                uint32_t ua, ub;
                asm("mov.b64 {%0, %1}, %2;" : "=r"(ua), "=r"(ub) : "l"(d2p));
                float d2a = __uint_as_float(ua), d2b = __uint_as_float(ub);
                float ra = __frsqrt_rn(d2a), rb = __frsqrt_rn(d2b);
                // m = max(0.1 - d2*rsqrt(d2), 0);  d2==0 -> NaN -> fmaxf gives 0
                float ma = fmaxf(fmaf(-d2a, ra, MIN_DISTF), 0.f);
                float mb = fmaxf(fmaf(-d2b, rb, MIN_DISTF), 0.f);
                acc0 = fmaf(ma, ma, acc0);
                acc1 = fmaf(mb, mb, acc1);
            }
        } else {
            // straddles the diagonal: keep only j > i  (k > i - jbase locally)
            const int ilocal = i - jbase;
#pragma unroll 8
            for (int k = 0; k < JCH; k += 2) {
                uint64_t xk, yk, dxp, dyp, t, d2p;
                asm("ld.shared.b64 %0, [%1];" : "=l"(xk) : "r"(nxb + k * 4));
                asm("ld.shared.b64 %0, [%1];" : "=l"(yk) : "r"(nyb + k * 4));
                asm("add.rn.f32x2 %0, %1, %2;" : "=l"(dxp) : "l"(pix2), "l"(xk));
                asm("add.rn.f32x2 %0, %1, %2;" : "=l"(dyp) : "l"(piy2), "l"(yk));
                asm("mul.rn.f32x2 %0, %1, %1;" : "=l"(t)   : "l"(dxp));
                asm("fma.rn.f32x2 %0, %1, %1, %2;" : "=l"(d2p) : "l"(dyp), "l"(t));
                uint32_t ua, ub;
                asm("mov.b64 {%0, %1}, %2;" : "=r"(ua), "=r"(ub) : "l"(d2p));
                float d2a = __uint_as_float(ua), d2b = __uint_as_float(ub);
                float ra = __frsqrt_rn(d2a), rb = __frsqrt_rn(d2b);
                float ma = fmaxf(fmaf(-d2a, ra, MIN_DISTF), 0.f);
                float mb = fmaxf(fmaf(-d2b, rb, MIN_DISTF), 0.f);
                if (k     <= ilocal) ma = 0.f;
                if (k + 1 <= ilocal) mb = 0.f;
                acc0 = fmaf(ma, ma, acc0);
                acc1 = fmaf(mb, mb, acc1);
            }
        }
    }

    // ---- block reduction of (pen, mse) ----
    float pen = acc0 + acc1;
    const int lane = tid & 31, w = tid >> 5;
#pragma unroll
    for (int o = 16; o > 0; o >>= 1) {
        pen += __shfl_xor_sync(0xffffffffu, pen, o);
        mse += __shfl_xor_sync(0xffffffffu, mse, o);
    }
    if (lane == 0) { redp[w] = pen; redm[w] = mse; }
    __syncthreads();
    if (tid == 0) {
        float ps = 0.f, ms = 0.f;
#pragma unroll
        for (int x = 0; x < TPB / 32; x++) { ps += redp[x]; ms += redm[x]; }
        g_pen[bid] = ps;
        g_mse[bid] = ms;
        __threadfence();
        int ticket = atomicAdd(&g_cnt, 1);
        lastFlag = (ticket == NBLK - 1);
    }
    __syncthreads();

    // ---- last block finishes: deterministic final reduction in fp64 ----
    if (lastFlag) {
        if (w == 0) {
            double ps = 0.0, ms = 0.0;
#pragma unroll
            for (int x = 0; x < NBLK / 32; x++) {
                ps += (double)__ldcg(&g_pen[lane + x * 32]);
                ms += (double)__ldcg(&g_mse[lane + x * 32]);
            }
#pragma unroll
            for (int o = 16; o > 0; o >>= 1) {
                ps += __shfl_xor_sync(0xffffffffu, ps, o);
                ms += __shfl_xor_sync(0xffffffffu, ms, o);
            }
            if (lane == 0) {
                out[0] = (float)(ms * (1.0 / (double)(NPTS * 2)) + ps);
                g_cnt  = 0;  // reset for next (graph-replayed) launch
            }
        }
    }
}

extern "C" void kernel_launch(void* const* d_in, const int* in_sizes, int n_in,
                              void* d_out, int out_size) {
    const float* pred = (const float*)d_in[0];
    const float* targ = (const float*)d_in[1];
    k_fused<<<dim3(GRIDX, GRIDY), TPB>>>((const float4*)pred,
                                         (const float4*)targ,
                                         (const float2*)pred,
                                         (float*)d_out);
}

// round 3
// speedup vs baseline: 1.0194x; 1.0194x over previous
#include <cuda_runtime.h>

#define NPTS  8192
#define TPB   256
#define TI    512              // i-tile: 2 i-points per thread
#define TJ    256              // j-tile in shared
#define GX    (NPTS / TI)      // 16
#define GY    (NPTS / TJ)      // 32
#define NBLK  (GX * GY)        // 512
#define MIN_DISTF 0.1f

__device__ float g_pen[NBLK];
__device__ float g_mse[NBLK];
__device__ int   g_cnt = 0;    // last arriving block resets to 0 -> graph-replay safe

__global__ void __launch_bounds__(TPB) k_fused(const float4* __restrict__ pred4,
                                               const float4* __restrict__ targ4,
                                               const float2* __restrict__ pts,
                                               float* __restrict__ out) {
    __shared__ float2 tj[TJ];
    __shared__ float  redp[TPB / 32];
    __shared__ float  redm[TPB / 32];
    __shared__ int    lastFlag;

    const int tid   = threadIdx.x;
    const int bid   = blockIdx.y * gridDim.x + blockIdx.x;
    const int ibase = blockIdx.x * TI;
    const int jbase = blockIdx.y * TJ;

    // ---- MSE slice: 8 float4 per block (4096 total over 512 blocks) ----
    float mse = 0.f;
    if (tid < 8) {
        float4 a = pred4[bid * 8 + tid];
        float4 b = targ4[bid * 8 + tid];
        float d0 = a.x - b.x, d1 = a.y - b.y, d2 = a.z - b.z, d3 = a.w - b.w;
        mse = fmaf(d0, d0, fmaf(d1, d1, fmaf(d2, d2, d3 * d3)));
    }

    // ---- pairwise penalty over strict upper triangle ----
    float acc0 = 0.f, acc1 = 0.f;
    const bool active = (jbase + TJ > ibase);   // block-uniform
    if (active) {
        const int    i0 = ibase + tid;
        const int    i1 = i0 + TPB;
        const float2 p0 = pts[i0];
        const float2 p1 = pts[i1];

        tj[tid] = pts[jbase + tid];             // TJ == TPB
        __syncthreads();

        if (jbase >= ibase + TI) {
            // tile entirely strictly above the diagonal: no per-pair check.
            // d2==0 cannot occur here (distinct random points), and even the
            // j==i self-pair case is excluded by tiling.
#pragma unroll 8
            for (int k = 0; k < TJ; k++) {
                float2 q  = tj[k];
                float dx0 = p0.x - q.x, dy0 = p0.y - q.y;
                float dx1 = p1.x - q.x, dy1 = p1.y - q.y;
                float d20 = fmaf(dy0, dy0, dx0 * dx0);
                float d21 = fmaf(dy1, dy1, dx1 * dx1);
                float r0  = __frsqrt_rn(d20);
                float r1  = __frsqrt_rn(d21);
                float m0  = fmaxf(fmaf(d20, -r0, MIN_DISTF), 0.f);
                float m1  = fmaxf(fmaf(d21, -r1, MIN_DISTF), 0.f);
                acc0 = fmaf(m0, m0, acc0);
                acc1 = fmaf(m1, m1, acc1);
            }
        } else {
            // straddles the diagonal: keep only j > i.
            // (j==i gives d2==0 -> rsqrt=inf -> fma NaN -> fmaxf(NaN,0)=0,
            //  but the explicit check already zeroes it.)
#pragma unroll 8
            for (int k = 0; k < TJ; k++) {
                int    j  = jbase + k;
                float2 q  = tj[k];
                float dx0 = p0.x - q.x, dy0 = p0.y - q.y;
                float dx1 = p1.x - q.x, dy1 = p1.y - q.y;
                float d20 = fmaf(dy0, dy0, dx0 * dx0);
                float d21 = fmaf(dy1, dy1, dx1 * dx1);
                float r0  = __frsqrt_rn(d20);
                float r1  = __frsqrt_rn(d21);
                float m0  = fmaxf(fmaf(d20, -r0, MIN_DISTF), 0.f);
                float m1  = fmaxf(fmaf(d21, -r1, MIN_DISTF), 0.f);
                m0 = (j > i0) ? m0 : 0.f;
                m1 = (j > i1) ? m1 : 0.f;
                acc0 = fmaf(m0, m0, acc0);
                acc1 = fmaf(m1, m1, acc1);
            }
        }
    }

    // ---- block reduction ----
    float pen = acc0 + acc1;
    const int lane = tid & 31, w = tid >> 5;
#pragma unroll
    for (int o = 16; o > 0; o >>= 1) {
        pen += __shfl_xor_sync(0xffffffffu, pen, o);
        mse += __shfl_xor_sync(0xffffffffu, mse, o);
    }
    if (lane == 0) { redp[w] = pen; redm[w] = mse; }
    __syncthreads();
    if (tid == 0) {
        float ps = 0.f, ms = 0.f;
#pragma unroll
        for (int x = 0; x < TPB / 32; x++) { ps += redp[x]; ms += redm[x]; }
        g_pen[bid] = ps;
        g_mse[bid] = ms;
        __threadfence();
        int ticket = atomicAdd(&g_cnt, 1);
        lastFlag = (ticket == NBLK - 1);
    }
    __syncthreads();

    // ---- last block: deterministic fp64 final reduction ----
    if (lastFlag && w == 0) {
        double ps = 0.0, ms = 0.0;
#pragma unroll
        for (int x = 0; x < NBLK / 32; x++) {
            ps += (double)__ldcg(&g_pen[lane + x * 32]);
            ms += (double)__ldcg(&g_mse[lane + x * 32]);
        }
#pragma unroll
        for (int o = 16; o > 0; o >>= 1) {
            ps += __shfl_xor_sync(0xffffffffu, ps, o);
            ms += __shfl_xor_sync(0xffffffffu, ms, o);
        }
        if (lane == 0) {
            out[0] = (float)(ms * (1.0 / (double)(NPTS * 2)) + ps);
            g_cnt  = 0;
        }
    }
}

extern "C" void kernel_launch(void* const* d_in, const int* in_sizes, int n_in,
                              void* d_out, int out_size) {
    const float* pred = (const float*)d_in[0];
    const float* targ = (const float*)d_in[1];
    k_fused<<<dim3(GX, GY), TPB>>>((const float4*)pred,
                                   (const float4*)targ,
                                   (const float2*)pred,
                                   (float*)d_out);
}

// round 4
// speedup vs baseline: 2.4541x; 2.4073x over previous
#include <cuda_runtime.h>

#define NPTS  8192
#define TPB   256
#define TI    512              // i-tile: 2 i-points per thread
#define TJ    256              // j-tile in shared
#define GX    (NPTS / TI)      // 16
#define GY    (NPTS / TJ)      // 32
#define NBLK  (GX * GY)        // 512
#define MIN_DISTF 0.1f

__device__ float g_pen[NBLK];
__device__ float g_mse[NBLK];
__device__ int   g_cnt = 0;    // last arriving block resets to 0 -> graph-replay safe

// single-instruction MUFU.RSQ (NOT __frsqrt_rn, which expands to ~20 instrs)
__device__ __forceinline__ float rsq(float x) {
    float r;
    asm("rsqrt.approx.f32 %0, %1;" : "=f"(r) : "f"(x));
    return r;
}

__global__ void __launch_bounds__(TPB) k_fused(const float4* __restrict__ pred4,
                                               const float4* __restrict__ targ4,
                                               const float2* __restrict__ pts,
                                               float* __restrict__ out) {
    __shared__ float2 tj[TJ];
    __shared__ float  redp[TPB / 32];
    __shared__ float  redm[TPB / 32];
    __shared__ int    lastFlag;

    const int tid   = threadIdx.x;
    const int bid   = blockIdx.y * gridDim.x + blockIdx.x;
    const int ibase = blockIdx.x * TI;
    const int jbase = blockIdx.y * TJ;

    // ---- MSE slice: 8 float4 per block (4096 total over 512 blocks) ----
    float mse = 0.f;
    if (tid < 8) {
        float4 a = pred4[bid * 8 + tid];
        float4 b = targ4[bid * 8 + tid];
        float d0 = a.x - b.x, d1 = a.y - b.y, d2 = a.z - b.z, d3 = a.w - b.w;
        mse = fmaf(d0, d0, fmaf(d1, d1, fmaf(d2, d2, d3 * d3)));
    }

    // ---- pairwise penalty over strict upper triangle ----
    float acc0 = 0.f, acc1 = 0.f;
    const bool active = (jbase + TJ > ibase);   // block-uniform
    if (active) {
        const int    i0 = ibase + tid;
        const int    i1 = i0 + TPB;
        const float2 p0 = pts[i0];
        const float2 p1 = pts[i1];

        tj[tid] = pts[jbase + tid];             // TJ == TPB
        __syncthreads();

        if (jbase >= ibase + TI) {
            // tile entirely strictly above the diagonal: no per-pair check
#pragma unroll 16
            for (int k = 0; k < TJ; k++) {
                float2 q  = tj[k];
                float dx0 = p0.x - q.x, dy0 = p0.y - q.y;
                float dx1 = p1.x - q.x, dy1 = p1.y - q.y;
                float d20 = fmaf(dy0, dy0, dx0 * dx0);
                float d21 = fmaf(dy1, dy1, dx1 * dx1);
                float r0  = rsq(d20);
                float r1  = rsq(d21);
                float m0  = fmaxf(fmaf(d20, -r0, MIN_DISTF), 0.f);
                float m1  = fmaxf(fmaf(d21, -r1, MIN_DISTF), 0.f);
                acc0 = fmaf(m0, m0, acc0);
                acc1 = fmaf(m1, m1, acc1);
            }
        } else {
            // straddles the diagonal: keep only j > i
#pragma unroll 16
            for (int k = 0; k < TJ; k++) {
                int    j  = jbase + k;
                float2 q  = tj[k];
                float dx0 = p0.x - q.x, dy0 = p0.y - q.y;
                float dx1 = p1.x - q.x, dy1 = p1.y - q.y;
                float d20 = fmaf(dy0, dy0, dx0 * dx0);
                float d21 = fmaf(dy1, dy1, dx1 * dx1);
                float r0  = rsq(d20);
                float r1  = rsq(d21);
                float m0  = fmaxf(fmaf(d20, -r0, MIN_DISTF), 0.f);
                float m1  = fmaxf(fmaf(d21, -r1, MIN_DISTF), 0.f);
                m0 = (j > i0) ? m0 : 0.f;
                m1 = (j > i1) ? m1 : 0.f;
                acc0 = fmaf(m0, m0, acc0);
                acc1 = fmaf(m1, m1, acc1);
            }
        }
    }

    // ---- block reduction ----
    float pen = acc0 + acc1;
    const int lane = tid & 31, w = tid >> 5;
#pragma unroll
    for (int o = 16; o > 0; o >>= 1) {
        pen += __shfl_xor_sync(0xffffffffu, pen, o);
        mse += __shfl_xor_sync(0xffffffffu, mse, o);
    }
    if (lane == 0) { redp[w] = pen; redm[w] = mse; }
    __syncthreads();
    if (tid == 0) {
        float ps = 0.f, ms = 0.f;
#pragma unroll
        for (int x = 0; x < TPB / 32; x++) { ps += redp[x]; ms += redm[x]; }
        g_pen[bid] = ps;
        g_mse[bid] = ms;
        __threadfence();
        int ticket = atomicAdd(&g_cnt, 1);
        lastFlag = (ticket == NBLK - 1);
    }
    __syncthreads();

    // ---- last block: deterministic fp64 final reduction ----
    if (lastFlag && w == 0) {
        double ps = 0.0, ms = 0.0;
#pragma unroll
        for (int x = 0; x < NBLK / 32; x++) {
            ps += (double)__ldcg(&g_pen[lane + x * 32]);
            ms += (double)__ldcg(&g_mse[lane + x * 32]);
        }
#pragma unroll
        for (int o = 16; o > 0; o >>= 1) {
            ps += __shfl_xor_sync(0xffffffffu, ps, o);
            ms += __shfl_xor_sync(0xffffffffu, ms, o);
        }
        if (lane == 0) {
            out[0] = (float)(ms * (1.0 / (double)(NPTS * 2)) + ps);
            g_cnt  = 0;
        }
    }
}

extern "C" void kernel_launch(void* const* d_in, const int* in_sizes, int n_in,
                              void* d_out, int out_size) {
    const float* pred = (const float*)d_in[0];
    const float* targ = (const float*)d_in[1];
    k_fused<<<dim3(GX, GY), TPB>>>((const float4*)pred,
                                   (const float4*)targ,
                                   (const float2*)pred,
                                   (float*)d_out);
}

// round 5
// speedup vs baseline: 3.9697x; 1.6176x over previous
#include <cuda_runtime.h>

#define NPTS  8192
#define TPB   256
#define TI    512              // i-tile: 2 i-points per thread
#define TJ    256              // j-tile in shared (SoA)
#define NBLK  272              // exactly the active upper-triangle tiles (34 x 8)
#define MIN_DISTF 0.1f

__device__ float g_pen[NBLK];
__device__ float g_mse[NBLK];
__device__ int   g_cnt = 0;    // last arriving block resets to 0 -> graph-replay safe

// single-instruction MUFU.RSQ
__device__ __forceinline__ float rsq(float x) {
    float r;
    asm("rsqrt.approx.f32 %0, %1;" : "=f"(r) : "f"(x));
    return r;
}

// one pair, branchless; d2==0 -> NaN -> fmaxf -> 0 (self-pair safe)
#define PAIR(px, py, qx, qy, acc)                         \
    {                                                     \
        float dx_ = (px) - (qx), dy_ = (py) - (qy);       \
        float d2_ = fmaf(dx_, dx_, dy_ * dy_);            \
        float r_  = rsq(d2_);                             \
        float m_  = fmaxf(fmaf(d2_, -r_, MIN_DISTF), 0.f);\
        (acc) = fmaf(m_, m_, (acc));                      \
    }

#define PAIRP(px, py, qx, qy, acc, keep)                  \
    {                                                     \
        float dx_ = (px) - (qx), dy_ = (py) - (qy);       \
        float d2_ = fmaf(dx_, dx_, dy_ * dy_);            \
        float r_  = rsq(d2_);                             \
        float m_  = fmaxf(fmaf(d2_, -r_, MIN_DISTF), 0.f);\
        m_ = (keep) ? m_ : 0.f;                           \
        (acc) = fmaf(m_, m_, (acc));                      \
    }

__global__ void __launch_bounds__(TPB) k_fused(const float4* __restrict__ pred4,
                                               const float4* __restrict__ targ4,
                                               const float2* __restrict__ pts,
                                               float* __restrict__ out) {
    __shared__ __align__(16) float xs[TJ];
    __shared__ __align__(16) float ys[TJ];
    __shared__ float redp[TPB / 32];
    __shared__ float redm[TPB / 32];
    __shared__ int   lastFlag;

    const int tid = threadIdx.x;
    const int bid = blockIdx.y * 34 + blockIdx.x;

    // ---- decode (34 x 8) grid -> active tile (bx, by) via row-pair folding ----
    // row bx has 32-2bx active tiles; rows (p, 15-p) together have exactly 34.
    const int p = blockIdx.y;      // 0..7
    const int s = blockIdx.x;      // 0..33
    const int c = 32 - 2 * p;
    int bx, by;
    if (s < c) { bx = p;      by = 2 * p + s; }
    else       { bx = 15 - p; by = s - 2;     }
    const int ibase = bx * TI;
    const int jbase = by * TJ;

    // ---- MSE slice: 16 float4 per block (4096 total, guarded) ----
    float mse = 0.f;
    if (tid < 16) {
        int idx = bid * 16 + tid;
        if (idx < (NPTS * 2) / 4) {
            float4 a = pred4[idx];
            float4 b = targ4[idx];
            float d0 = a.x - b.x, d1 = a.y - b.y, d2 = a.z - b.z, d3 = a.w - b.w;
            mse = fmaf(d0, d0, fmaf(d1, d1, fmaf(d2, d2, d3 * d3)));
        }
    }

    // ---- load SoA j-tile ----
    {
        float2 q = pts[jbase + tid];
        xs[tid] = q.x;
        ys[tid] = q.y;
    }
    const int    i0 = ibase + tid;
    const int    i1 = i0 + TPB;
    const float2 p0 = pts[i0];
    const float2 p1 = pts[i1];
    __syncthreads();

    const float4* qx4 = reinterpret_cast<const float4*>(xs);
    const float4* qy4 = reinterpret_cast<const float4*>(ys);

    float a0 = 0.f, a1 = 0.f, a2 = 0.f, a3 = 0.f;
    float a4 = 0.f, a5 = 0.f, a6 = 0.f, a7 = 0.f;

    if (by >= 2 * bx + 2) {
        // tile entirely strictly above the diagonal: no per-pair check
#pragma unroll 4
        for (int k4 = 0; k4 < TJ / 4; k4++) {
            float4 qx = qx4[k4];
            float4 qy = qy4[k4];
            PAIR(p0.x, p0.y, qx.x, qy.x, a0);
            PAIR(p0.x, p0.y, qx.y, qy.y, a1);
            PAIR(p0.x, p0.y, qx.z, qy.z, a2);
            PAIR(p0.x, p0.y, qx.w, qy.w, a3);
            PAIR(p1.x, p1.y, qx.x, qy.x, a4);
            PAIR(p1.x, p1.y, qx.y, qy.y, a5);
            PAIR(p1.x, p1.y, qx.z, qy.z, a6);
            PAIR(p1.x, p1.y, qx.w, qy.w, a7);
        }
    } else {
        // straddles the diagonal: keep only j > i
#pragma unroll 4
        for (int k4 = 0; k4 < TJ / 4; k4++) {
            float4 qx = qx4[k4];
            float4 qy = qy4[k4];
            int j0 = jbase + 4 * k4;
            PAIRP(p0.x, p0.y, qx.x, qy.x, a0, j0 + 0 > i0);
            PAIRP(p0.x, p0.y, qx.y, qy.y, a1, j0 + 1 > i0);
            PAIRP(p0.x, p0.y, qx.z, qy.z, a2, j0 + 2 > i0);
            PAIRP(p0.x, p0.y, qx.w, qy.w, a3, j0 + 3 > i0);
            PAIRP(p1.x, p1.y, qx.x, qy.x, a4, j0 + 0 > i1);
            PAIRP(p1.x, p1.y, qx.y, qy.y, a5, j0 + 1 > i1);
            PAIRP(p1.x, p1.y, qx.z, qy.z, a6, j0 + 2 > i1);
            PAIRP(p1.x, p1.y, qx.w, qy.w, a7, j0 + 3 > i1);
        }
    }

    // ---- block reduction ----
    float pen = ((a0 + a1) + (a2 + a3)) + ((a4 + a5) + (a6 + a7));
    const int lane = tid & 31, w = tid >> 5;
#pragma unroll
    for (int o = 16; o > 0; o >>= 1) {
        pen += __shfl_xor_sync(0xffffffffu, pen, o);
        mse += __shfl_xor_sync(0xffffffffu, mse, o);
    }
    if (lane == 0) { redp[w] = pen; redm[w] = mse; }
    __syncthreads();
    if (tid == 0) {
        float ps = 0.f, ms = 0.f;
#pragma unroll
        for (int x = 0; x < TPB / 32; x++) { ps += redp[x]; ms += redm[x]; }
        g_pen[bid] = ps;
        g_mse[bid] = ms;
        __threadfence();
        int ticket = atomicAdd(&g_cnt, 1);
        lastFlag = (ticket == NBLK - 1);
    }
    __syncthreads();

    // ---- last block: deterministic fp64 final reduction ----
    if (lastFlag && w == 0) {
        double ps = 0.0, ms = 0.0;
#pragma unroll
        for (int x = 0; x < 9; x++) {
            int idx = lane + x * 32;
            if (idx < NBLK) {
                ps += (double)__ldcg(&g_pen[idx]);
                ms += (double)__ldcg(&g_mse[idx]);
            }
        }
#pragma unroll
        for (int o = 16; o > 0; o >>= 1) {
            ps += __shfl_xor_sync(0xffffffffu, ps, o);
            ms += __shfl_xor_sync(0xffffffffu, ms, o);
        }
        if (lane == 0) {
            out[0] = (float)(ms * (1.0 / (double)(NPTS * 2)) + ps);
            g_cnt  = 0;
        }
    }
}

extern "C" void kernel_launch(void* const* d_in, const int* in_sizes, int n_in,
                              void* d_out, int out_size) {
    const float* pred = (const float*)d_in[0];
    const float* targ = (const float*)d_in[1];
    k_fused<<<dim3(34, 8), TPB>>>((const float4*)pred,
                                  (const float4*)targ,
                                  (const float2*)pred,
                                  (float*)d_out);
}